// round 14
// baseline (speedup 1.0000x reference)
#include <cuda_runtime.h>

#define TPB   128
#define NR    32768
#define DD    64
#define HH    8
#define PP    14
#define KB    5
#define NCH   16           // dim chunks; chunk c owns dims ≡ c (mod 16)
#define NRB   128          // row-blocks of 256 rows
#define ROWS  256          // rows per CTA (2 per thread)
#define BBf   5.0f
#define MINW  0.001f
#define MINH  0.001f
#define MIND  0.001f
#define XST   65           // padded smem stride -> conflict-free column reads
#define BLOB  736          // u64 per blob: w2[64] w3[128] b1[8] b2[8] b3[16] w1[<=512]
#define OFF_W2 0
#define OFF_W3 64
#define OFF_B1 192
#define OFF_B2 200
#define OFF_B3 208
#define OFF_W1 224

#define SMEM_XSH   (ROWS * XST * 4)            // 66560
#define SMEM_WBUF  (2 * BLOB * 8)              // 11776
#define SMEM_TOTAL (SMEM_XSH + SMEM_WBUF + 256)

typedef unsigned long long u64;

// prepacked weights: 32 blobs (pidx = k*16 + chunk), pair (da, da+16), da = chunk + 32k
__device__ __align__(16) u64 g_pack[32 * BLOB];

__device__ __forceinline__ u64 ffma2(u64 a, u64 b, u64 c){
    u64 d; asm("fma.rn.f32x2 %0, %1, %2, %3;" : "=l"(d) : "l"(a), "l"(b), "l"(c)); return d;
}
__device__ __forceinline__ u64 pack2(float lo, float hi){
    u64 d; asm("mov.b64 %0, {%1, %2};" : "=l"(d) : "f"(lo), "f"(hi)); return d;
}
__device__ __forceinline__ void unpack2(u64 v, float& lo, float& hi){
    asm("mov.b64 {%0, %1}, %2;" : "=f"(lo), "=f"(hi) : "l"(v));
}
__device__ __forceinline__ float tanh_fast(float x){
    float y; asm("tanh.approx.f32 %0, %1;" : "=f"(y) : "f"(x)); return y;
}
__device__ __forceinline__ unsigned smem_u32(const void* p){
    return (unsigned)__cvta_generic_to_shared(p);
}
__device__ __forceinline__ void mbar_init(unsigned a, unsigned cnt){
    asm volatile("mbarrier.init.shared.b64 [%0], %1;" :: "r"(a), "r"(cnt) : "memory");
}
__device__ __forceinline__ void mbar_expect_tx(unsigned a, unsigned bytes){
    asm volatile("mbarrier.arrive.expect_tx.shared.b64 _, [%0], %1;" :: "r"(a), "r"(bytes) : "memory");
}
__device__ __forceinline__ void mbar_wait(unsigned a, unsigned phase){
    asm volatile(
        "{\n\t.reg .pred P;\n\t"
        "WAITLP_%=:\n\t"
        "mbarrier.try_wait.parity.acquire.cta.shared::cta.b64 P, [%0], %1, 0x989680;\n\t"
        "@P bra.uni WAITDN_%=;\n\t"
        "bra.uni WAITLP_%=;\n\t"
        "WAITDN_%=:\n\t}"
        :: "r"(a), "r"(phase) : "memory");
}
__device__ __forceinline__ void bulk_g2s(unsigned dst, const void* src, unsigned bytes, unsigned mbar){
    asm volatile(
        "cp.async.bulk.shared::cta.global.mbarrier::complete_tx::bytes [%0], [%1], %2, [%3];"
        :: "r"(dst), "l"(src), "r"(bytes), "r"(mbar) : "memory");
}

// ---------------- prepack kernel: interleave (lo,hi) weight pairs ----------------
__global__ void prepack_kernel(const float* __restrict__ W1, const float* __restrict__ b1,
                               const float* __restrict__ W2, const float* __restrict__ b2,
                               const float* __restrict__ W3, const float* __restrict__ b3)
{
    const int pidx  = blockIdx.x;        // k*16 + chunk
    const int k     = pidx >> 4;
    const int chunk = pidx & 15;
    const int da = chunk + 32 * k;       // lo dim of pair (da, da+16)
    const int la = da - 1;               // may be -1 (lo lane zeros)
    const int lb = da + 15;              // (da+16) - 1
    u64* dst = g_pack + (size_t)pidx * BLOB;
    const int tid = threadIdx.x;

    if (tid < 64){
        float lo = (la >= 0) ? W2[la * 64 + tid] : 0.f;
        dst[OFF_W2 + tid] = pack2(lo, W2[lb * 64 + tid]);
    }
    if (tid < 128){                      // w3: 8 rows x 16 padded cols
        int g = tid >> 4, c = tid & 15;
        u64 v = 0ULL;
        if (c < PP){
            float lo = (la >= 0) ? W3[la * (HH*PP) + g * PP + c] : 0.f;
            v = pack2(lo, W3[lb * (HH*PP) + g * PP + c]);
        }
        dst[OFF_W3 + tid] = v;
    }
    if (tid < HH){
        float l1v = (la >= 0) ? b1[la * HH + tid] : 0.f;
        dst[OFF_B1 + tid] = pack2(l1v, b1[lb * HH + tid]);
        float l2v = (la >= 0) ? b2[la * HH + tid] : 0.f;
        dst[OFF_B2 + tid] = pack2(l2v, b2[lb * HH + tid]);
    }
    if (tid < 16){
        u64 v = 0ULL;
        if (tid < PP){
            float lo = (la >= 0) ? b3[la * PP + tid] : 0.f;
            v = pack2(lo, b3[lb * PP + tid]);
        }
        dst[OFF_B3 + tid] = v;
    }
    const int n1 = (lb + 1) * HH;
    const float* W1a = W1 + (size_t)la * (63*HH);
    const float* W1b = W1 + (size_t)lb * (63*HH);
    for (int e = tid; e < n1; e += blockDim.x){
        float lo = (la >= 0) ? W1a[e] : 0.f;     // input W1 is pre-masked: rows > la are 0
        dst[OFF_W1 + e] = pack2(lo, W1b[e]);
    }
}

// Two independent RQS evaluations, interleaved for 2-way ILP through MUFU chains.
__device__ __forceinline__ void rqs_eval2(const float* pa, float xa,
                                          const float* pb, float xb,
                                          float& za, float& lda,
                                          float& zb, float& ldb)
{
    bool ina = (xa >= -BBf) && (xa <= BBf);
    bool inb = (xb >= -BBf) && (xb <= BBf);
    float xca = fminf(fmaxf(xa, -BBf), BBf);
    float xcb = fminf(fmaxf(xb, -BBf), BBf);

    float ewa[KB], eha[KB], ewb[KB], ehb[KB];
    float swa = 0.f, sha = 0.f, swb = 0.f, shb = 0.f;
#pragma unroll
    for (int k = 0; k < KB; k++){
        ewa[k] = __expf(pa[k]);      ewb[k] = __expf(pb[k]);
        swa += ewa[k];               swb += ewb[k];
    }
#pragma unroll
    for (int k = 0; k < KB; k++){
        eha[k] = __expf(pa[KB + k]); ehb[k] = __expf(pb[KB + k]);
        sha += eha[k];               shb += ehb[k];
    }
    float aWa = __fdividef(1.0f - KB * MINW, swa);
    float aWb = __fdividef(1.0f - KB * MINW, swb);
    float aHa = __fdividef(1.0f - KB * MINH, sha);
    float aHb = __fdividef(1.0f - KB * MINH, shb);

    float cwa = -BBf, cha = -BBf, cwb = -BBf, chb = -BBf;
    float icwa = -BBf, icha = -BBf, ibwa = 1.f, iha = 1.f;
    float icwb = -BBf, ichb = -BBf, ibwb = 1.f, ihb = 1.f;
    float duLa = 0.f, duRa = 0.f, duLb = 0.f, duRb = 0.f;
    bool fba = true, lba = false, fbb = true, lbb = false;
#pragma unroll
    for (int k = 0; k < KB; k++){
        float nwa = (k == KB-1) ? BBf : cwa + 2.0f * BBf * (MINW + aWa * ewa[k]);
        float nwb = (k == KB-1) ? BBf : cwb + 2.0f * BBf * (MINW + aWb * ewb[k]);
        float nha = (k == KB-1) ? BBf : cha + 2.0f * BBf * (MINH + aHa * eha[k]);
        float nhb = (k == KB-1) ? BBf : chb + 2.0f * BBf * (MINH + aHb * ehb[k]);
        bool ca = (k == 0) || (xca >= cwa);
        bool cb = (k == 0) || (xcb >= cwb);
        if (ca){
            icwa = cwa; icha = cha; ibwa = nwa - cwa; iha = nha - cha;
            fba = (k == 0); lba = (k == KB-1);
            duLa = (k == 0)    ? 0.f : pa[2*KB + k - 1];
            duRa = (k == KB-1) ? 0.f : pa[2*KB + k];
        }
        if (cb){
            icwb = cwb; ichb = chb; ibwb = nwb - cwb; ihb = nhb - chb;
            fbb = (k == 0); lbb = (k == KB-1);
            duLb = (k == 0)    ? 0.f : pb[2*KB + k - 1];
            duRb = (k == KB-1) ? 0.f : pb[2*KB + k];
        }
        cwa = nwa; cha = nha; cwb = nwb; chb = nhb;
    }
    float idva  = fba ? 1.0f : (MIND + __logf(1.0f + __expf(duLa)));
    float idvb  = fbb ? 1.0f : (MIND + __logf(1.0f + __expf(duLb)));
    float idp1a = lba ? 1.0f : (MIND + __logf(1.0f + __expf(duRa)));
    float idp1b = lbb ? 1.0f : (MIND + __logf(1.0f + __expf(duRb)));

    float rba = __fdividef(1.0f, ibwa);
    float rbb = __fdividef(1.0f, ibwb);
    float tha = (xca - icwa) * rba;
    float thb = (xcb - icwb) * rbb;
    float idla = iha * rba;
    float idlb = ihb * rbb;
    float tma = tha * (1.0f - tha);
    float tmb = thb * (1.0f - thb);
    float t2a = tha * tha;
    float t2b = thb * thb;
    float numa = iha * (idla * t2a + idva * tma);
    float numb = ihb * (idlb * t2b + idvb * tmb);
    float dena = idla + (idva + idp1a - 2.0f * idla) * tma;
    float denb = idlb + (idvb + idp1b - 2.0f * idlb) * tmb;
    float outa = icha + __fdividef(numa, dena);
    float outb = ichb + __fdividef(numb, denb);
    float oma = 1.0f - tha;
    float omb = 1.0f - thb;
    float dna = idla * idla * (idp1a * t2a + 2.0f * idla * tma + idva * oma * oma);
    float dnb = idlb * idlb * (idp1b * t2b + 2.0f * idlb * tmb + idvb * omb * omb);
    float lva = __logf(dna) - 2.0f * __logf(dena);
    float lvb = __logf(dnb) - 2.0f * __logf(denb);

    za  = ina ? outa : xa;
    zb  = inb ? outb : xb;
    lda = ina ? lva  : 0.0f;
    ldb = inb ? lvb  : 0.0f;
}

__global__ __launch_bounds__(TPB)
void nsf_ar_kernel(const float* __restrict__ x,
                   const float* __restrict__ initp,
                   float* __restrict__ out)
{
    extern __shared__ __align__(16) char smem[];
    float* xsh      = (float*)smem;                          // ROWS*XST floats
    u64*   wbuf0    = (u64*)(smem + SMEM_XSH);               // BLOB u64
    u64*   wbuf1    = wbuf0 + BLOB;
    u64*   mbar     = (u64*)(smem + SMEM_XSH + SMEM_WBUF);   // [2]
    float* redf     = (float*)(mbar + 2);                    // [2][16]

    const int tid    = threadIdx.x;
    const int warp   = tid >> 5;
    const int bid    = blockIdx.x;          // 0..2047
    const int chunk  = bid & (NCH - 1);     // 0..15
    const int rowblk = bid >> 4;            // 0..127
    const int row0   = rowblk * ROWS;
    const int rowA   = row0 + tid;          // sub-tile A
    const int rowB   = row0 + 128 + tid;    // sub-tile B

    const unsigned a_full0 = smem_u32(mbar);
    const unsigned a_full1 = smem_u32(mbar + 1);

    if (tid == 0){ mbar_init(a_full0, 1); mbar_init(a_full1, 1); }

    // stage x tile (256 rows) with float4 global reads
    {
        const float4* X4 = (const float4*)(x + (size_t)row0 * DD);
        for (int i = tid; i < ROWS * DD / 4; i += TPB){
            float4 v = X4[i];
            int r = i >> 4, c = (i & 15) * 4;
            float* d = &xsh[r * XST + c];
            d[0] = v.x; d[1] = v.y; d[2] = v.z; d[3] = v.w;
        }
    }
    __syncthreads();   // mbar init + xsh visible

    if (tid == 0){
        asm volatile("fence.proxy.async.shared::cta;" ::: "memory");
        // prefetch BOTH pair blobs now; 2 buffers, 2 uses, no reuse protocol needed
        unsigned sz0 = (unsigned)((OFF_W1 + (chunk + 16) * HH) * 8);
        mbar_expect_tx(a_full0, sz0);
        bulk_g2s(smem_u32(wbuf0), (const void*)(g_pack + (size_t)chunk * BLOB), sz0, a_full0);
        unsigned sz1 = (unsigned)((OFF_W1 + (chunk + 48) * HH) * 8);
        mbar_expect_tx(a_full1, sz1);
        bulk_g2s(smem_u32(wbuf1), (const void*)(g_pack + (size_t)(16 + chunk) * BLOB), sz1, a_full1);
    }

    const float* xrA = &xsh[tid * XST];
    const float* xrB = &xsh[(tid + 128) * XST];
    float* out2 = out + (size_t)NR * DD;

#pragma unroll
    for (int k = 0; k < 2; k++){
        const int da = chunk + 32 * k;
        const int db = da + 16;
        const int lb = da + 15;             // shared j bound (lo lane masked beyond la)
        const u64* wb = k ? wbuf1 : wbuf0;

        mbar_wait(k ? a_full1 : a_full0, 0);

        // ---- layer 1: two rows share every weight fetch ----
        u64 a1A[HH], a1B[HH];
#pragma unroll
        for (int h = 0; h < HH; h++){ a1A[h] = wb[OFF_B1 + h]; a1B[h] = a1A[h]; }
#pragma unroll 2
        for (int j = 0; j <= lb; j++){
            float xa = xrA[j], xb = xrB[j];
            u64 xpA = pack2(xa, xa), xpB = pack2(xb, xb);
            const ulonglong2* wp = reinterpret_cast<const ulonglong2*>(&wb[OFF_W1 + j * 8]);
            ulonglong2 q0 = wp[0], q1 = wp[1], q2 = wp[2], q3 = wp[3];
            a1A[0] = ffma2(xpA, q0.x, a1A[0]); a1B[0] = ffma2(xpB, q0.x, a1B[0]);
            a1A[1] = ffma2(xpA, q0.y, a1A[1]); a1B[1] = ffma2(xpB, q0.y, a1B[1]);
            a1A[2] = ffma2(xpA, q1.x, a1A[2]); a1B[2] = ffma2(xpB, q1.x, a1B[2]);
            a1A[3] = ffma2(xpA, q1.y, a1A[3]); a1B[3] = ffma2(xpB, q1.y, a1B[3]);
            a1A[4] = ffma2(xpA, q2.x, a1A[4]); a1B[4] = ffma2(xpB, q2.x, a1B[4]);
            a1A[5] = ffma2(xpA, q2.y, a1A[5]); a1B[5] = ffma2(xpB, q2.y, a1B[5]);
            a1A[6] = ffma2(xpA, q3.x, a1A[6]); a1B[6] = ffma2(xpB, q3.x, a1B[6]);
            a1A[7] = ffma2(xpA, q3.y, a1A[7]); a1B[7] = ffma2(xpB, q3.y, a1B[7]);
        }

        float ldaA, ldbA, ldaB, ldbB;

        // ---- per-row tail: layers 2/3 + spline (row-sequential to bound registers) ----
#pragma unroll
        for (int rsel = 0; rsel < 2; rsel++){
            u64* a1 = rsel ? a1B : a1A;
            const float* xr = rsel ? xrB : xrA;
            const int row  = rsel ? rowB : rowA;

            u64 a1t[HH];
#pragma unroll
            for (int h = 0; h < HH; h++){
                float lo, hi; unpack2(a1[h], lo, hi);
                a1t[h] = pack2(tanh_fast(lo), tanh_fast(hi));
            }

            u64 a2[HH];
#pragma unroll
            for (int g = 0; g < HH; g++) a2[g] = wb[OFF_B2 + g];
#pragma unroll
            for (int h = 0; h < HH; h++){
                u64 hv = a1t[h];
                const ulonglong2* wp = reinterpret_cast<const ulonglong2*>(&wb[OFF_W2 + h * 8]);
                ulonglong2 q0 = wp[0], q1 = wp[1], q2 = wp[2], q3 = wp[3];
                a2[0] = ffma2(hv, q0.x, a2[0]); a2[1] = ffma2(hv, q0.y, a2[1]);
                a2[2] = ffma2(hv, q1.x, a2[2]); a2[3] = ffma2(hv, q1.y, a2[3]);
                a2[4] = ffma2(hv, q2.x, a2[4]); a2[5] = ffma2(hv, q2.y, a2[5]);
                a2[6] = ffma2(hv, q3.x, a2[6]); a2[7] = ffma2(hv, q3.y, a2[7]);
            }
#pragma unroll
            for (int g = 0; g < HH; g++){
                float lo, hi; unpack2(a2[g], lo, hi);
                a2[g] = pack2(tanh_fast(lo), tanh_fast(hi));
            }

            u64 pu[16];
#pragma unroll
            for (int c = 0; c < 16; c++) pu[c] = wb[OFF_B3 + c];
#pragma unroll
            for (int g = 0; g < HH; g++){
                u64 gv = a2[g];
                const ulonglong2* wp = reinterpret_cast<const ulonglong2*>(&wb[OFF_W3 + g * 16]);
                ulonglong2 q0 = wp[0], q1 = wp[1], q2 = wp[2], q3 = wp[3];
                ulonglong2 q4 = wp[4], q5 = wp[5], q6 = wp[6];
                pu[0]  = ffma2(gv, q0.x, pu[0]);  pu[1]  = ffma2(gv, q0.y, pu[1]);
                pu[2]  = ffma2(gv, q1.x, pu[2]);  pu[3]  = ffma2(gv, q1.y, pu[3]);
                pu[4]  = ffma2(gv, q2.x, pu[4]);  pu[5]  = ffma2(gv, q2.y, pu[5]);
                pu[6]  = ffma2(gv, q3.x, pu[6]);  pu[7]  = ffma2(gv, q3.y, pu[7]);
                pu[8]  = ffma2(gv, q4.x, pu[8]);  pu[9]  = ffma2(gv, q4.y, pu[9]);
                pu[10] = ffma2(gv, q5.x, pu[10]); pu[11] = ffma2(gv, q5.y, pu[11]);
                pu[12] = ffma2(gv, q6.x, pu[12]); pu[13] = ffma2(gv, q6.y, pu[13]);
            }

            float pa[PP], pb[PP];
#pragma unroll
            for (int c = 0; c < PP; c++) unpack2(pu[c], pa[c], pb[c]);
            if (da == 0){
#pragma unroll
                for (int c = 0; c < PP; c++) pa[c] = initp[c];
            }

            float za, lda, zb, ldb;
            rqs_eval2(pa, xr[da], pb, xr[db], za, lda, zb, ldb);
            out[(size_t)da * NR + row] = za;
            out[(size_t)db * NR + row] = zb;
            if (rsel){ ldaB = lda; ldbB = ldb; } else { ldaA = lda; ldbA = ldb; }
        }

        // ---- logdet partial sums ----
#pragma unroll
        for (int o = 16; o > 0; o >>= 1){
            ldaA += __shfl_down_sync(0xffffffffu, ldaA, o);
            ldbA += __shfl_down_sync(0xffffffffu, ldbA, o);
            ldaB += __shfl_down_sync(0xffffffffu, ldaB, o);
            ldbB += __shfl_down_sync(0xffffffffu, ldbB, o);
        }
        float* red = redf + k * 16;
        if ((tid & 31) == 0){
            red[warp]      = ldaA;   // v0: da, sub A
            red[4 + warp]  = ldbA;   // v1: db, sub A
            red[8 + warp]  = ldaB;   // v2: da, sub B
            red[12 + warp] = ldbB;   // v3: db, sub B
        }
        __syncthreads();
        if (tid < 8){
            int dimsel = tid >> 2;              // 0: da, 1: db
            int g      = tid & 3;               // 64-row group 0..3
            int v      = (g >> 1) * 2 + dimsel; // sub(A/B)*2 + dim
            int gg     = g & 1;                 // warp-pair within sub-tile
            float s = red[v * 4 + 2 * gg] + red[v * 4 + 2 * gg + 1];
            int dim = dimsel ? db : da;
            out2[dim * (NR/64) + rowblk * 4 + g] = s;
        }
        // next k writes redf[1] (distinct), reads guarded by its own __syncthreads
    }
}

extern "C" void kernel_launch(void* const* d_in, const int* in_sizes, int n_in,
                              void* d_out, int out_size)
{
    const float* x     = (const float*)d_in[0];
    const float* initp = (const float*)d_in[1];
    const float* W1    = (const float*)d_in[2];
    const float* b1    = (const float*)d_in[3];
    const float* W2    = (const float*)d_in[4];
    const float* b2    = (const float*)d_in[5];
    const float* W3    = (const float*)d_in[6];
    const float* b3    = (const float*)d_in[7];
    float* out = (float*)d_out;

    static int configured = 0;
    if (!configured){
        cudaFuncSetAttribute(nsf_ar_kernel,
                             cudaFuncAttributeMaxDynamicSharedMemorySize, SMEM_TOTAL);
        configured = 1;
    }

    prepack_kernel<<<32, TPB>>>(W1, b1, W2, b2, W3, b3);
    nsf_ar_kernel<<<NRB * NCH, TPB, SMEM_TOTAL>>>(x, initp, out);
}